// round 1
// baseline (speedup 1.0000x reference)
#include <cuda_runtime.h>

#define D 256
#define BM 32
#define KT 8
#define MAXN 100000

// Scratch (allocation-free rule: __device__ globals)
__device__ float g_msg[(size_t)MAXN * D];
__device__ float g_deg[MAXN];
__device__ float g_tmp[(size_t)MAXN * D];

// ---------------------------------------------------------------------------
// Zero msg[n*D] and deg[n]
__global__ void zero_kernel(float* __restrict__ msg, float* __restrict__ deg, int n) {
    int total4 = n * (D / 4);
    float4 z = make_float4(0.f, 0.f, 0.f, 0.f);
    float4* m4 = (float4*)msg;
    for (int i = blockIdx.x * blockDim.x + threadIdx.x; i < total4;
         i += gridDim.x * blockDim.x)
        m4[i] = z;
    for (int i = blockIdx.x * blockDim.x + threadIdx.x; i < n;
         i += gridDim.x * blockDim.x)
        deg[i] = 0.f;
}

// ---------------------------------------------------------------------------
// Edge scatter-add: one block (256 threads) per edge, one float per thread.
__global__ void scatter_kernel(const float* __restrict__ feat,
                               const int* __restrict__ src,
                               const int* __restrict__ dst,
                               float* __restrict__ msg,
                               float* __restrict__ deg,
                               int nE) {
    int e = blockIdx.x;
    if (e >= nE) return;
    int s = src[e], d = dst[e];
    float v = feat[s * D + threadIdx.x];
    atomicAdd(&msg[d * D + threadIdx.x], v);
    if (threadIdx.x == 0) atomicAdd(&deg[d], 1.0f);
}

// ---------------------------------------------------------------------------
// Fused: out = [h, msg/max(deg,1)] @ W1 + b1 -> relu -> @ W2 + b2 -> +h -> (LN)
// BM=32 rows per block, full N=256. 256 threads, per-thread 4x8 micro-tile.
// warp ty owns rows ty*4..ty*4+3 entirely -> LN via warp shuffle only.
__global__ __launch_bounds__(256) void mlp_kernel(
    const float* __restrict__ h,
    const float* __restrict__ msg,
    const float* __restrict__ deg,
    const float* __restrict__ w1, const float* __restrict__ b1,
    const float* __restrict__ w2, const float* __restrict__ b2,
    const float* __restrict__ lng, const float* __restrict__ lnb,
    float* __restrict__ out, int M, int use_ln)
{
    __shared__ float xs[BM][KT];
    __shared__ float ws[KT][D];
    __shared__ float hid[BM][D];
    __shared__ float rdeg[BM];

    int tid = threadIdx.x;
    int tx = tid & 31, ty = tid >> 5;
    int row0 = blockIdx.x * BM;

    if (tid < BM) {
        int r = row0 + tid;
        float dg = (r < M) ? deg[r] : 1.f;
        rdeg[tid] = 1.f / fmaxf(dg, 1.f);
    }
    __syncthreads();

    float acc[4][8];
#pragma unroll
    for (int r = 0; r < 4; r++)
#pragma unroll
        for (int j = 0; j < 8; j++) acc[r][j] = 0.f;

    // ---- phase 1: hidden = relu(x @ W1 + b1), K = 2*D ----
    for (int kt = 0; kt < 2 * D; kt += KT) {
        {   // x tile: 32 rows x 8 k, one element per thread
            int rr = tid >> 3, kk = tid & 7;
            int row = row0 + rr;
            int k = kt + kk;
            float v = 0.f;
            if (row < M) {
                if (k < D) v = h[row * D + k];
                else       v = msg[row * D + (k - D)] * rdeg[rr];
            }
            xs[rr][kk] = v;
        }
        // w1 tile: 8 x 256, float4 loads, 2 per thread
#pragma unroll
        for (int i = 0; i < 2; i++) {
            int idx4 = (tid + i * 256) * 4;
            int kk = idx4 >> 8, n = idx4 & 255;
            *(float4*)&ws[kk][n] = *(const float4*)&w1[(kt + kk) * D + n];
        }
        __syncthreads();
#pragma unroll
        for (int kk = 0; kk < KT; kk++) {
            float a0 = xs[ty * 4 + 0][kk];
            float a1 = xs[ty * 4 + 1][kk];
            float a2 = xs[ty * 4 + 2][kk];
            float a3 = xs[ty * 4 + 3][kk];
#pragma unroll
            for (int j = 0; j < 8; j++) {
                float b = ws[kk][tx + 32 * j];
                acc[0][j] += a0 * b;
                acc[1][j] += a1 * b;
                acc[2][j] += a2 * b;
                acc[3][j] += a3 * b;
            }
        }
        __syncthreads();
    }
    // epilogue 1: bias + relu -> smem hidden; reset acc
#pragma unroll
    for (int j = 0; j < 8; j++) {
        int col = tx + 32 * j;
        float bb = b1[col];
#pragma unroll
        for (int r = 0; r < 4; r++) {
            hid[ty * 4 + r][col] = fmaxf(acc[r][j] + bb, 0.f);
            acc[r][j] = 0.f;
        }
    }
    __syncthreads();

    // ---- phase 2: out = hidden @ W2 + b2 + h (+ LN), K = D ----
    for (int kt = 0; kt < D; kt += KT) {
#pragma unroll
        for (int i = 0; i < 2; i++) {
            int idx4 = (tid + i * 256) * 4;
            int kk = idx4 >> 8, n = idx4 & 255;
            *(float4*)&ws[kk][n] = *(const float4*)&w2[(kt + kk) * D + n];
        }
        __syncthreads();
#pragma unroll
        for (int kk = 0; kk < KT; kk++) {
            float a0 = hid[ty * 4 + 0][kt + kk];
            float a1 = hid[ty * 4 + 1][kt + kk];
            float a2 = hid[ty * 4 + 2][kt + kk];
            float a3 = hid[ty * 4 + 3][kt + kk];
#pragma unroll
            for (int j = 0; j < 8; j++) {
                float b = ws[kk][tx + 32 * j];
                acc[0][j] += a0 * b;
                acc[1][j] += a1 * b;
                acc[2][j] += a2 * b;
                acc[3][j] += a3 * b;
            }
        }
        __syncthreads();
    }

    // epilogue 2: bias + residual (+ LayerNorm) + store
#pragma unroll
    for (int r = 0; r < 4; r++) {
        int row = row0 + ty * 4 + r;
        bool valid = row < M;
        float v[8];
#pragma unroll
        for (int j = 0; j < 8; j++) {
            int col = tx + 32 * j;
            float res = valid ? h[row * D + col] : 0.f;
            v[j] = acc[r][j] + b2[col] + res;
        }
        if (use_ln) {
            float sum = 0.f, sq = 0.f;
#pragma unroll
            for (int j = 0; j < 8; j++) { sum += v[j]; sq += v[j] * v[j]; }
#pragma unroll
            for (int o = 16; o > 0; o >>= 1) {
                sum += __shfl_xor_sync(0xffffffffu, sum, o);
                sq  += __shfl_xor_sync(0xffffffffu, sq, o);
            }
            float mean = sum * (1.f / D);
            float var  = sq * (1.f / D) - mean * mean;
            float rstd = rsqrtf(var + 1e-5f);
#pragma unroll
            for (int j = 0; j < 8; j++) {
                int col = tx + 32 * j;
                v[j] = (v[j] - mean) * rstd * lng[col] + lnb[col];
            }
        }
        if (valid) {
#pragma unroll
            for (int j = 0; j < 8; j++)
                out[row * D + tx + 32 * j] = v[j];
        }
    }
}

// ---------------------------------------------------------------------------
static inline int cdiv(int a, int b) { return (a + b - 1) / b; }

extern "C" void kernel_launch(void* const* d_in, const int* in_sizes, int n_in,
                              void* d_out, int out_size) {
    const float* cell_h = (const float*)d_in[0];
    const float* net_h  = (const float*)d_in[1];
    const int* e_c2n = (const int*)d_in[2];
    const int* e_n2c = (const int*)d_in[3];
    const int* e_c2c = (const int*)d_in[4];
    const float* c2n_w1 = (const float*)d_in[5];
    const float* c2n_b1 = (const float*)d_in[6];
    const float* c2n_w2 = (const float*)d_in[7];
    const float* c2n_b2 = (const float*)d_in[8];
    const float* n2c_w1 = (const float*)d_in[9];
    const float* n2c_b1 = (const float*)d_in[10];
    const float* n2c_w2 = (const float*)d_in[11];
    const float* n2c_b2 = (const float*)d_in[12];
    const float* c2c_w1 = (const float*)d_in[13];
    const float* c2c_b1 = (const float*)d_in[14];
    const float* c2c_w2 = (const float*)d_in[15];
    const float* c2c_b2 = (const float*)d_in[16];
    const float* net_ln_g  = (const float*)d_in[17];
    const float* net_ln_b  = (const float*)d_in[18];
    const float* cell_ln_g = (const float*)d_in[19];
    const float* cell_ln_b = (const float*)d_in[20];

    int n_cell = in_sizes[0] / D;
    int n_net  = in_sizes[1] / D;
    int E1 = in_sizes[2] / 2;
    int E2 = in_sizes[3] / 2;
    int E3 = in_sizes[4] / 2;

    float* out = (float*)d_out;
    float* out_cell = out;                              // [n_cell, D]
    float* out_net  = out + (size_t)n_cell * D;         // [n_net, D]

    static float* p_msg = nullptr;
    static float* p_deg = nullptr;
    static float* p_tmp = nullptr;
    if (!p_msg) {
        cudaGetSymbolAddress((void**)&p_msg, g_msg);
        cudaGetSymbolAddress((void**)&p_deg, g_deg);
        cudaGetSymbolAddress((void**)&p_tmp, g_tmp);
    }

    // Stage 1: cells -> nets, then net_h' = LN(net_h + MLP([net_h, msg]))
    zero_kernel<<<2048, 256>>>(p_msg, p_deg, n_net);
    scatter_kernel<<<E1, 256>>>(cell_h, e_c2n, e_c2n + E1, p_msg, p_deg, E1);
    mlp_kernel<<<cdiv(n_net, BM), 256>>>(net_h, p_msg, p_deg,
                                         c2n_w1, c2n_b1, c2n_w2, c2n_b2,
                                         net_ln_g, net_ln_b,
                                         out_net, n_net, 1);

    // Stage 2: nets -> cells, cell_tmp = cell_h + MLP([cell_h, msg])
    zero_kernel<<<2048, 256>>>(p_msg, p_deg, n_cell);
    scatter_kernel<<<E2, 256>>>(out_net, e_n2c, e_n2c + E2, p_msg, p_deg, E2);
    mlp_kernel<<<cdiv(n_cell, BM), 256>>>(cell_h, p_msg, p_deg,
                                          n2c_w1, n2c_b1, n2c_w2, n2c_b2,
                                          (const float*)0, (const float*)0,
                                          p_tmp, n_cell, 0);

    // Stage 3: cells -> cells, cell_h' = LN(cell_tmp + MLP([cell_tmp, msg]))
    zero_kernel<<<2048, 256>>>(p_msg, p_deg, n_cell);
    scatter_kernel<<<E3, 256>>>(p_tmp, e_c2c, e_c2c + E3, p_msg, p_deg, E3);
    mlp_kernel<<<cdiv(n_cell, BM), 256>>>(p_tmp, p_msg, p_deg,
                                          c2c_w1, c2c_b1, c2c_w2, c2c_b2,
                                          cell_ln_g, cell_ln_b,
                                          out_cell, n_cell, 1);
}

// round 2
// speedup vs baseline: 1.8596x; 1.8596x over previous
#include <cuda_runtime.h>

#define D 256
#define MAXN 100000
#define BM 64
#define KT 32
#define PA 36      // As row stride (floats)
#define PB 33      // Bs row stride (floats), swizzled transposed layout
#define PH 260     // hid row stride (floats)

// Scratch (allocation-free rule: __device__ globals)
__device__ float g_msg[(size_t)MAXN * D];
__device__ float g_deg[MAXN];
__device__ float g_tmp[(size_t)MAXN * D];

// ---------------------------------------------------------------------------
__global__ void zero_kernel(float* __restrict__ msg, float* __restrict__ deg, int n) {
    int total4 = n * (D / 4);
    float4 z = make_float4(0.f, 0.f, 0.f, 0.f);
    float4* m4 = (float4*)msg;
    for (int i = blockIdx.x * blockDim.x + threadIdx.x; i < total4;
         i += gridDim.x * blockDim.x)
        m4[i] = z;
    for (int i = blockIdx.x * blockDim.x + threadIdx.x; i < n;
         i += gridDim.x * blockDim.x)
        deg[i] = 0.f;
}

// ---------------------------------------------------------------------------
// warp-per-edge scatter: each lane gathers 2 float4 and does 8 scalar atomics.
__global__ __launch_bounds__(256) void scatter_kernel(
        const float* __restrict__ feat,
        const int* __restrict__ src,
        const int* __restrict__ dst,
        float* __restrict__ msg,
        float* __restrict__ deg,
        int nE) {
    int warp = (blockIdx.x * blockDim.x + threadIdx.x) >> 5;
    int lane = threadIdx.x & 31;
    if (warp >= nE) return;
    int s = src[warp], d = dst[warp];
    const float4* f4 = (const float4*)(feat + (size_t)s * D);
    float* mrow = msg + (size_t)d * D;
#pragma unroll
    for (int i = 0; i < 2; i++) {
        int c4 = lane + 32 * i;
        float4 v = f4[c4];
        atomicAdd(mrow + 4 * c4 + 0, v.x);
        atomicAdd(mrow + 4 * c4 + 1, v.y);
        atomicAdd(mrow + 4 * c4 + 2, v.z);
        atomicAdd(mrow + 4 * c4 + 3, v.w);
    }
    if (lane == 0) atomicAdd(&deg[d], 1.0f);
}

// ---------------------------------------------------------------------------
// msg[row] *= 1/max(deg[row],1)
__global__ void norm_kernel(float* __restrict__ msg, const float* __restrict__ deg,
                            int n) {
    int i = blockIdx.x * blockDim.x + threadIdx.x;
    int total4 = n * (D / 4);
    if (i >= total4) return;
    int row = i >> 6;
    float r = 1.f / fmaxf(deg[row], 1.f);
    float4 v = ((float4*)msg)[i];
    v.x *= r; v.y *= r; v.z *= r; v.w *= r;
    ((float4*)msg)[i] = v;
}

// ---------------------------------------------------------------------------
__device__ __forceinline__ void mma_tf32(float* c, const unsigned* a, const unsigned* b) {
    asm volatile(
        "mma.sync.aligned.m16n8k8.row.col.f32.tf32.tf32.f32 "
        "{%0,%1,%2,%3}, {%4,%5,%6,%7}, {%8,%9}, {%0,%1,%2,%3};"
        : "+f"(c[0]), "+f"(c[1]), "+f"(c[2]), "+f"(c[3])
        : "r"(a[0]), "r"(a[1]), "r"(a[2]), "r"(a[3]), "r"(b[0]), "r"(b[1]));
}

// Fused MLP: out = [h, msg] @ W1 + b1 -> relu -> @ W2 + b2 -> +h -> (LN)
// Block: 64 rows x 256 cols, 8 warps (4 warp_m x 2 warp_n), tf32 tensor cores.
__global__ __launch_bounds__(256) void mlp_mma_kernel(
    const float* __restrict__ h,
    const float* __restrict__ msg,
    const float* __restrict__ w1, const float* __restrict__ b1,
    const float* __restrict__ w2, const float* __restrict__ b2,
    const float* __restrict__ lng, const float* __restrict__ lnb,
    float* __restrict__ out, int M, int use_ln)
{
    extern __shared__ float sm[];
    float* As  = sm;                         // [64][PA]
    float* Bs  = sm + BM * PA;               // [256][PB] transposed + swizzled
    float* hid = sm + BM * PA + D * PB;      // [64][PH]

    int tid = threadIdx.x;
    int lane = tid & 31, w = tid >> 5;
    int grp = lane >> 2, tig = lane & 3;
    int wm = w & 3, wn = w >> 2;
    int m0 = wm * 16;
    int nbase = wn * 128;
    int row0 = blockIdx.x * BM;

    float acc[16][4];
#pragma unroll
    for (int i = 0; i < 16; i++)
#pragma unroll
        for (int j = 0; j < 4; j++) acc[i][j] = 0.f;

    int bk = tid >> 3;   // 0..31: k-row within tile
    int bg = tid & 7;    // 0..7

    float4 Bv[8];
    float4 Av[2];

    // ---- helpers ----
    auto loadB = [&](const float* __restrict__ W, int kt) {
        const float4* src = (const float4*)(W + (size_t)(kt + bk) * D);
#pragma unroll
        for (int i = 0; i < 8; i++) Bv[i] = src[bg + 8 * i];
    };
    auto storeB = [&]() {
#pragma unroll
        for (int i = 0; i < 8; i++) {
            int nb = 4 * (bg + 8 * i);
            Bs[(nb + 0) * PB + (bk ^ (((nb + 0) & 7) << 2))] = Bv[i].x;
            Bs[(nb + 1) * PB + (bk ^ (((nb + 1) & 7) << 2))] = Bv[i].y;
            Bs[(nb + 2) * PB + (bk ^ (((nb + 2) & 7) << 2))] = Bv[i].z;
            Bs[(nb + 3) * PB + (bk ^ (((nb + 3) & 7) << 2))] = Bv[i].w;
        }
    };
    auto loadA = [&](int kt) {
#pragma unroll
        for (int it = 0; it < 2; it++) {
            int m = (tid >> 3) + 32 * it;
            int row = row0 + m;
            int k = kt + 4 * bg;
            float4 v = make_float4(0.f, 0.f, 0.f, 0.f);
            if (row < M) {
                const float* src = (k < D) ? (h + (size_t)row * D + k)
                                           : (msg + (size_t)row * D + (k - D));
                v = *(const float4*)src;
            }
            Av[it] = v;
        }
    };
    auto storeA = [&]() {
#pragma unroll
        for (int it = 0; it < 2; it++) {
            int m = (tid >> 3) + 32 * it;
            *(float4*)(As + m * PA + 4 * bg) = Av[it];
        }
    };
    auto computeStep = [&](const float* __restrict__ Amat, int astride, int kofs) {
#pragma unroll
        for (int kb = 0; kb < 4; kb++) {
            unsigned a[4];
            int kc = kofs + kb * 8 + tig;
            a[0] = __float_as_uint(Amat[(m0 + grp) * astride + kc]);
            a[1] = __float_as_uint(Amat[(m0 + grp + 8) * astride + kc]);
            a[2] = __float_as_uint(Amat[(m0 + grp) * astride + kc + 4]);
            a[3] = __float_as_uint(Amat[(m0 + grp + 8) * astride + kc + 4]);
#pragma unroll
            for (int t2 = 0; t2 < 16; t2++) {
                int nb = nbase + 8 * t2 + grp;
                int sw = (nb & 7) << 2;
                unsigned b[2];
                b[0] = __float_as_uint(Bs[nb * PB + ((kb * 8 + tig) ^ sw)]);
                b[1] = __float_as_uint(Bs[nb * PB + ((kb * 8 + tig + 4) ^ sw)]);
                mma_tf32(acc[t2], a, b);
            }
        }
    };

    // ---- phase 1: hidden = relu(x @ W1 + b1), K = 512 ----
    loadA(0); loadB(w1, 0);
    for (int s = 0; s < 16; s++) {
        __syncthreads();
        storeA(); storeB();
        __syncthreads();
        if (s < 15) { loadA((s + 1) * KT); loadB(w1, (s + 1) * KT); }
        computeStep(As, PA, 0);
    }

    // epilogue 1: bias + relu -> hid; reset acc
#pragma unroll
    for (int t2 = 0; t2 < 16; t2++) {
        int c = nbase + 8 * t2 + 2 * tig;
        float bb0 = __ldg(b1 + c), bb1 = __ldg(b1 + c + 1);
        hid[(m0 + grp) * PH + c]     = fmaxf(acc[t2][0] + bb0, 0.f);
        hid[(m0 + grp) * PH + c + 1] = fmaxf(acc[t2][1] + bb1, 0.f);
        hid[(m0 + grp + 8) * PH + c]     = fmaxf(acc[t2][2] + bb0, 0.f);
        hid[(m0 + grp + 8) * PH + c + 1] = fmaxf(acc[t2][3] + bb1, 0.f);
#pragma unroll
        for (int j = 0; j < 4; j++) acc[t2][j] = 0.f;
    }

    // ---- phase 2: acc = hid @ W2, K = 256 ----
    loadB(w2, 0);
    for (int s = 0; s < 8; s++) {
        __syncthreads();   // also covers: all epilogue-1 hid writes visible
        storeB();
        __syncthreads();
        if (s < 7) loadB(w2, (s + 1) * KT);
        computeStep(hid, PH, s * KT);
    }

    // epilogue 2: raw acc -> hid (after everyone stops reading hid)
    __syncthreads();
#pragma unroll
    for (int t2 = 0; t2 < 16; t2++) {
        int c = nbase + 8 * t2 + 2 * tig;
        hid[(m0 + grp) * PH + c]         = acc[t2][0];
        hid[(m0 + grp) * PH + c + 1]     = acc[t2][1];
        hid[(m0 + grp + 8) * PH + c]     = acc[t2][2];
        hid[(m0 + grp + 8) * PH + c + 1] = acc[t2][3];
    }
    __syncthreads();

    // output pass: + b2 + residual (+ LN), coalesced. warp w owns rows 8w..8w+7
    for (int q = 0; q < 8; q++) {
        int r = w * 8 + q;
        int row = row0 + r;
        if (row >= M) continue;
        float v[8];
        float sum = 0.f, sq = 0.f;
#pragma unroll
        for (int j = 0; j < 8; j++) {
            int c = lane + 32 * j;
            float x = hid[r * PH + c] + __ldg(b2 + c) + h[(size_t)row * D + c];
            v[j] = x; sum += x; sq += x * x;
        }
        if (use_ln) {
#pragma unroll
            for (int o = 16; o > 0; o >>= 1) {
                sum += __shfl_xor_sync(0xffffffffu, sum, o);
                sq  += __shfl_xor_sync(0xffffffffu, sq, o);
            }
            float mean = sum * (1.f / D);
            float var  = sq * (1.f / D) - mean * mean;
            float rstd = rsqrtf(var + 1e-5f);
#pragma unroll
            for (int j = 0; j < 8; j++) {
                int c = lane + 32 * j;
                v[j] = (v[j] - mean) * rstd * __ldg(lng + c) + __ldg(lnb + c);
            }
        }
#pragma unroll
        for (int j = 0; j < 8; j++)
            out[(size_t)row * D + lane + 32 * j] = v[j];
    }
}

// ---------------------------------------------------------------------------
static inline int cdiv(int a, int b) { return (a + b - 1) / b; }

extern "C" void kernel_launch(void* const* d_in, const int* in_sizes, int n_in,
                              void* d_out, int out_size) {
    const float* cell_h = (const float*)d_in[0];
    const float* net_h  = (const float*)d_in[1];
    const int* e_c2n = (const int*)d_in[2];
    const int* e_n2c = (const int*)d_in[3];
    const int* e_c2c = (const int*)d_in[4];
    const float* c2n_w1 = (const float*)d_in[5];
    const float* c2n_b1 = (const float*)d_in[6];
    const float* c2n_w2 = (const float*)d_in[7];
    const float* c2n_b2 = (const float*)d_in[8];
    const float* n2c_w1 = (const float*)d_in[9];
    const float* n2c_b1 = (const float*)d_in[10];
    const float* n2c_w2 = (const float*)d_in[11];
    const float* n2c_b2 = (const float*)d_in[12];
    const float* c2c_w1 = (const float*)d_in[13];
    const float* c2c_b1 = (const float*)d_in[14];
    const float* c2c_w2 = (const float*)d_in[15];
    const float* c2c_b2 = (const float*)d_in[16];
    const float* net_ln_g  = (const float*)d_in[17];
    const float* net_ln_b  = (const float*)d_in[18];
    const float* cell_ln_g = (const float*)d_in[19];
    const float* cell_ln_b = (const float*)d_in[20];

    int n_cell = in_sizes[0] / D;
    int n_net  = in_sizes[1] / D;
    int E1 = in_sizes[2] / 2;
    int E2 = in_sizes[3] / 2;
    int E3 = in_sizes[4] / 2;

    float* out = (float*)d_out;
    float* out_cell = out;
    float* out_net  = out + (size_t)n_cell * D;

    static float* p_msg = nullptr;
    static float* p_deg = nullptr;
    static float* p_tmp = nullptr;
    if (!p_msg) {
        cudaGetSymbolAddress((void**)&p_msg, g_msg);
        cudaGetSymbolAddress((void**)&p_deg, g_deg);
        cudaGetSymbolAddress((void**)&p_tmp, g_tmp);
    }

    const int SMEM = (BM * PA + D * PB + BM * PH) * 4;  // 109,568 B
    cudaFuncSetAttribute(mlp_mma_kernel,
                         cudaFuncAttributeMaxDynamicSharedMemorySize, SMEM);

    // Stage 1: cells -> nets, net_h' = LN(net_h + MLP([net_h, mean_msg]))
    zero_kernel<<<2048, 256>>>(p_msg, p_deg, n_net);
    scatter_kernel<<<cdiv(E1 * 32, 256), 256>>>(cell_h, e_c2n, e_c2n + E1,
                                                p_msg, p_deg, E1);
    norm_kernel<<<cdiv(n_net * 64, 256), 256>>>(p_msg, p_deg, n_net);
    mlp_mma_kernel<<<cdiv(n_net, BM), 256, SMEM>>>(
        net_h, p_msg, c2n_w1, c2n_b1, c2n_w2, c2n_b2,
        net_ln_g, net_ln_b, out_net, n_net, 1);

    // Stage 2: nets -> cells, cell_tmp = cell_h + MLP([cell_h, mean_msg])
    zero_kernel<<<2048, 256>>>(p_msg, p_deg, n_cell);
    scatter_kernel<<<cdiv(E2 * 32, 256), 256>>>(out_net, e_n2c, e_n2c + E2,
                                                p_msg, p_deg, E2);
    norm_kernel<<<cdiv(n_cell * 64, 256), 256>>>(p_msg, p_deg, n_cell);
    mlp_mma_kernel<<<cdiv(n_cell, BM), 256, SMEM>>>(
        cell_h, p_msg, n2c_w1, n2c_b1, n2c_w2, n2c_b2,
        (const float*)0, (const float*)0, p_tmp, n_cell, 0);

    // Stage 3: cells -> cells, cell_h' = LN(cell_tmp + MLP([cell_tmp, mean_msg]))
    zero_kernel<<<2048, 256>>>(p_msg, p_deg, n_cell);
    scatter_kernel<<<cdiv(E3 * 32, 256), 256>>>(p_tmp, e_c2c, e_c2c + E3,
                                                p_msg, p_deg, E3);
    norm_kernel<<<cdiv(n_cell * 64, 256), 256>>>(p_msg, p_deg, n_cell);
    mlp_mma_kernel<<<cdiv(n_cell, BM), 256, SMEM>>>(
        p_tmp, p_msg, c2c_w1, c2c_b1, c2c_w2, c2c_b2,
        cell_ln_g, cell_ln_b, out_cell, n_cell, 1);
}

// round 4
// speedup vs baseline: 2.7520x; 1.4799x over previous
#include <cuda_runtime.h>

#define D 256
#define MAXN 100000
#define BM 64
#define KT 16
#define PA 20      // As row stride (floats): banks (20g+t)%32 all distinct
#define PBN 264    // Bs row stride (floats): banks (8*tig+grp) distinct
#define PH 260     // hid row stride (floats): banks (4g+t) distinct

#define ASZ (BM * PA)        // 1280 floats per A buffer
#define BSZ (KT * PBN)       // 4224 floats per B buffer
#define SM_BS (2 * ASZ)                // Bs offset (floats)
#define SM_HID (2 * ASZ + 2 * BSZ)     // hid offset (floats)
#define SMEM_BYTES ((2 * ASZ + 2 * BSZ + BM * PH) * 4)  // 110592 B

// Scratch (allocation-free rule: __device__ globals)
__device__ float g_msg[(size_t)MAXN * D];
__device__ float g_deg[MAXN];
__device__ float g_tmp[(size_t)MAXN * D];

// ---------------------------------------------------------------------------
__global__ void zero_kernel(float* __restrict__ msg, float* __restrict__ deg, int n) {
    int total4 = n * (D / 4);
    float4 z = make_float4(0.f, 0.f, 0.f, 0.f);
    float4* m4 = (float4*)msg;
    for (int i = blockIdx.x * blockDim.x + threadIdx.x; i < total4;
         i += gridDim.x * blockDim.x)
        m4[i] = z;
    for (int i = blockIdx.x * blockDim.x + threadIdx.x; i < n;
         i += gridDim.x * blockDim.x)
        deg[i] = 0.f;
}

// ---------------------------------------------------------------------------
__device__ __forceinline__ void red_add_v4(float* p, float4 v) {
    asm volatile("red.global.add.v4.f32 [%0], {%1,%2,%3,%4};"
                 :: "l"(p), "f"(v.x), "f"(v.y), "f"(v.z), "f"(v.w) : "memory");
}

// warp-per-edge scatter: each lane gathers 2 float4, 2 vector red ops.
__global__ __launch_bounds__(256) void scatter_kernel(
        const float* __restrict__ feat,
        const int* __restrict__ src,
        const int* __restrict__ dst,
        float* __restrict__ msg,
        float* __restrict__ deg,
        int nE) {
    int warp = (blockIdx.x * blockDim.x + threadIdx.x) >> 5;
    int lane = threadIdx.x & 31;
    if (warp >= nE) return;
    int s = __ldg(src + warp), d = __ldg(dst + warp);
    const float4* f4 = (const float4*)(feat + (size_t)s * D);
    float* mrow = msg + (size_t)d * D;
    float4 v0 = __ldg(f4 + lane);
    float4 v1 = __ldg(f4 + lane + 32);
    red_add_v4(mrow + 4 * lane, v0);
    red_add_v4(mrow + 4 * (lane + 32), v1);
    if (lane == 0) atomicAdd(&deg[d], 1.0f);
}

// ---------------------------------------------------------------------------
__device__ __forceinline__ void mma_tf32(float* c, const unsigned* a,
                                         unsigned b0, unsigned b1) {
    asm volatile(
        "mma.sync.aligned.m16n8k8.row.col.f32.tf32.tf32.f32 "
        "{%0,%1,%2,%3}, {%4,%5,%6,%7}, {%8,%9}, {%0,%1,%2,%3};"
        : "+f"(c[0]), "+f"(c[1]), "+f"(c[2]), "+f"(c[3])
        : "r"(a[0]), "r"(a[1]), "r"(a[2]), "r"(a[3]), "r"(b0), "r"(b1));
}

__device__ __forceinline__ void cp16(unsigned dst, const void* src, int nbytes) {
    asm volatile("cp.async.cg.shared.global [%0], [%1], 16, %2;"
                 :: "r"(dst), "l"(src), "r"(nbytes));
}
__device__ __forceinline__ void cp_commit() {
    asm volatile("cp.async.commit_group;");
}
template <int N>
__device__ __forceinline__ void cp_wait() {
    asm volatile("cp.async.wait_group %0;" :: "n"(N));
}

// ---------------------------------------------------------------------------
// Fused MLP: out = [h, msg*rdeg] @ W1 + b1 -> relu -> @ W2 + b2 -> +h -> (LN)
// 64 rows x 256 cols per block, 8 warps (4 wm x 2 wn), tf32 mma, cp.async
// double-buffered tiles, 2 CTAs/SM.
__global__ __launch_bounds__(256, 2) void mlp_mma_kernel(
    const float* __restrict__ h,
    const float* __restrict__ msg,
    const float* __restrict__ deg,
    const float* __restrict__ w1, const float* __restrict__ b1,
    const float* __restrict__ w2, const float* __restrict__ b2,
    const float* __restrict__ lng, const float* __restrict__ lnb,
    float* __restrict__ out, int M, int use_ln)
{
    extern __shared__ float smf[];
    float* As  = smf;             // [2][64][PA]
    float* Bs  = smf + SM_BS;     // [2][KT][PBN]
    float* hid = smf + SM_HID;    // [64][PH]
    unsigned sbase = (unsigned)__cvta_generic_to_shared(smf);
    unsigned As_s = sbase;
    unsigned Bs_s = sbase + SM_BS * 4;

    int tid = threadIdx.x;
    int lane = tid & 31, w = tid >> 5;
    int grp = lane >> 2, tig = lane & 3;
    int wm = w & 3, wn = w >> 2;
    int m0 = wm * 16;
    int nbase = wn * 128;
    int row0 = blockIdx.x * BM;

    // degree reciprocal for this thread's two A rows
    int rA = row0 + m0 + grp;
    float rd0 = 1.f, rd1 = 1.f;
    if (rA < M)     rd0 = 1.f / fmaxf(__ldg(deg + rA), 1.f);
    if (rA + 8 < M) rd1 = 1.f / fmaxf(__ldg(deg + rA + 8), 1.f);

    float acc[16][4];
#pragma unroll
    for (int i = 0; i < 16; i++)
#pragma unroll
        for (int j = 0; j < 4; j++) acc[i][j] = 0.f;

    // --- cp.async producer indices ---
    int arow = tid >> 2, achunk = tid & 3;            // A: 64 rows x 16 floats
    int aval = (row0 + arow < M) ? 16 : 0;
    int arowc = (row0 + arow < M) ? (row0 + arow) : (M - 1);
    unsigned a_dst0 = As_s + (unsigned)(arow * PA + achunk * 4) * 4;
    int bk = tid >> 4, bseg = tid & 15;               // B: 16 rows x 256 floats
    unsigned b_dst0 = Bs_s + (unsigned)(bk * PBN + bseg * 16) * 4;

    auto issueA = [&](int s, int buf) {
        int k0 = s * KT;
        const float* srcp = (k0 < D)
            ? (h   + (size_t)arowc * D + k0 + achunk * 4)
            : (msg + (size_t)arowc * D + (k0 - D) + achunk * 4);
        cp16(a_dst0 + buf * (ASZ * 4), srcp, aval);
    };
    auto issueB = [&](const float* __restrict__ W, int s, int buf) {
        const float* srcp = W + (size_t)(s * KT + bk) * D + bseg * 16;
        unsigned dst = b_dst0 + buf * (BSZ * 4);
#pragma unroll
        for (int i = 0; i < 4; i++)
            cp16(dst + 16 * i, srcp + 4 * i, 16);
    };

    auto computeStep = [&](const float* __restrict__ Ab, int astride, int kbase,
                           const float* __restrict__ Bb, bool scaleA) {
#pragma unroll
        for (int kb = 0; kb < 2; kb++) {
            int kc = kbase + kb * 8 + tig;
            float a0 = Ab[(m0 + grp) * astride + kc];
            float a1 = Ab[(m0 + grp + 8) * astride + kc];
            float a2 = Ab[(m0 + grp) * astride + kc + 4];
            float a3 = Ab[(m0 + grp + 8) * astride + kc + 4];
            if (scaleA) { a0 *= rd0; a1 *= rd1; a2 *= rd0; a3 *= rd1; }
            unsigned au[4] = {__float_as_uint(a0), __float_as_uint(a1),
                              __float_as_uint(a2), __float_as_uint(a3)};
            const float* Br0 = Bb + (kb * 8 + tig) * PBN;
            const float* Br1 = Bb + (kb * 8 + tig + 4) * PBN;
#pragma unroll
            for (int t2 = 0; t2 < 16; t2++) {
                int n = nbase + 8 * t2 + grp;
                mma_tf32(acc[t2], au,
                         __float_as_uint(Br0[n]), __float_as_uint(Br1[n]));
            }
        }
    };

    // ---- phase 1: hidden = relu(x @ W1 + b1), K = 512, 32 steps ----
    issueA(0, 0); issueB(w1, 0, 0); cp_commit();
#pragma unroll 1
    for (int s = 0; s < 32; s++) {
        if (s < 31) {
            issueA(s + 1, (s + 1) & 1); issueB(w1, s + 1, (s + 1) & 1);
            cp_commit();
            cp_wait<1>();
        } else {
            cp_wait<0>();
        }
        __syncthreads();
        computeStep(As + (s & 1) * ASZ, PA, 0, Bs + (s & 1) * BSZ, s >= 16);
        __syncthreads();
    }

    // prefetch first W2 tile while doing epilogue 1
    issueB(w2, 0, 0); cp_commit();

    // epilogue 1: bias + relu -> hid; reset acc
#pragma unroll
    for (int t2 = 0; t2 < 16; t2++) {
        int c = nbase + 8 * t2 + 2 * tig;
        float bb0 = __ldg(b1 + c), bb1 = __ldg(b1 + c + 1);
        hid[(m0 + grp) * PH + c]         = fmaxf(acc[t2][0] + bb0, 0.f);
        hid[(m0 + grp) * PH + c + 1]     = fmaxf(acc[t2][1] + bb1, 0.f);
        hid[(m0 + grp + 8) * PH + c]     = fmaxf(acc[t2][2] + bb0, 0.f);
        hid[(m0 + grp + 8) * PH + c + 1] = fmaxf(acc[t2][3] + bb1, 0.f);
#pragma unroll
        for (int j = 0; j < 4; j++) acc[t2][j] = 0.f;
    }

    // ---- phase 2: acc = hid @ W2, K = 256, 16 steps ----
#pragma unroll 1
    for (int s = 0; s < 16; s++) {
        if (s < 15) {
            issueB(w2, s + 1, (s + 1) & 1);
            cp_commit();
            cp_wait<1>();
        } else {
            cp_wait<0>();
        }
        __syncthreads();   // s==0: also publishes epilogue-1 hid writes
        computeStep(hid, PH, s * KT, Bs + (s & 1) * BSZ, false);
        __syncthreads();
    }

    // epilogue 2: raw acc -> hid (all phase-2 reads finished at loop's last sync)
#pragma unroll
    for (int t2 = 0; t2 < 16; t2++) {
        int c = nbase + 8 * t2 + 2 * tig;
        hid[(m0 + grp) * PH + c]         = acc[t2][0];
        hid[(m0 + grp) * PH + c + 1]     = acc[t2][1];
        hid[(m0 + grp + 8) * PH + c]     = acc[t2][2];
        hid[(m0 + grp + 8) * PH + c + 1] = acc[t2][3];
    }
    __syncthreads();

    // output pass: + b2 + residual (+ LN), coalesced; warp w owns rows 8w..8w+7
    for (int q = 0; q < 8; q++) {
        int r = w * 8 + q;
        int row = row0 + r;
        if (row >= M) continue;
        float v[8];
        float sum = 0.f, sq = 0.f;
#pragma unroll
        for (int j = 0; j < 8; j++) {
            int c = lane + 32 * j;
            float x = hid[r * PH + c] + __ldg(b2 + c) + h[(size_t)row * D + c];
            v[j] = x; sum += x; sq += x * x;
        }
        if (use_ln) {
#pragma unroll
            for (int o = 16; o > 0; o >>= 1) {
                sum += __shfl_xor_sync(0xffffffffu, sum, o);
                sq  += __shfl_xor_sync(0xffffffffu, sq, o);
            }
            float mean = sum * (1.f / D);
            float var  = sq * (1.f / D) - mean * mean;
            float rstd = rsqrtf(var + 1e-5f);
#pragma unroll
            for (int j = 0; j < 8; j++) {
                int c = lane + 32 * j;
                v[j] = (v[j] - mean) * rstd * __ldg(lng + c) + __ldg(lnb + c);
            }
        }
#pragma unroll
        for (int j = 0; j < 8; j++)
            out[(size_t)row * D + lane + 32 * j] = v[j];
    }
}

// ---------------------------------------------------------------------------
static inline int cdiv(int a, int b) { return (a + b - 1) / b; }

extern "C" void kernel_launch(void* const* d_in, const int* in_sizes, int n_in,
                              void* d_out, int out_size) {
    const float* cell_h = (const float*)d_in[0];
    const float* net_h  = (const float*)d_in[1];
    const int* e_c2n = (const int*)d_in[2];
    const int* e_n2c = (const int*)d_in[3];
    const int* e_c2c = (const int*)d_in[4];
    const float* c2n_w1 = (const float*)d_in[5];
    const float* c2n_b1 = (const float*)d_in[6];
    const float* c2n_w2 = (const float*)d_in[7];
    const float* c2n_b2 = (const float*)d_in[8];
    const float* n2c_w1 = (const float*)d_in[9];
    const float* n2c_b1 = (const float*)d_in[10];
    const float* n2c_w2 = (const float*)d_in[11];
    const float* n2c_b2 = (const float*)d_in[12];
    const float* c2c_w1 = (const float*)d_in[13];
    const float* c2c_b1 = (const float*)d_in[14];
    const float* c2c_w2 = (const float*)d_in[15];
    const float* c2c_b2 = (const float*)d_in[16];
    const float* net_ln_g  = (const float*)d_in[17];
    const float* net_ln_b  = (const float*)d_in[18];
    const float* cell_ln_g = (const float*)d_in[19];
    const float* cell_ln_b = (const float*)d_in[20];

    int n_cell = in_sizes[0] / D;
    int n_net  = in_sizes[1] / D;
    int E1 = in_sizes[2] / 2;
    int E2 = in_sizes[3] / 2;
    int E3 = in_sizes[4] / 2;

    float* out = (float*)d_out;
    float* out_cell = out;
    float* out_net  = out + (size_t)n_cell * D;

    static float* p_msg = nullptr;
    static float* p_deg = nullptr;
    static float* p_tmp = nullptr;
    if (!p_msg) {
        cudaGetSymbolAddress((void**)&p_msg, g_msg);
        cudaGetSymbolAddress((void**)&p_deg, g_deg);
        cudaGetSymbolAddress((void**)&p_tmp, g_tmp);
        cudaFuncSetAttribute(mlp_mma_kernel,
                             cudaFuncAttributeMaxDynamicSharedMemorySize,
                             SMEM_BYTES);
    }

    // Stage 1: cells -> nets, net_h' = LN(net_h + MLP([net_h, mean_msg]))
    zero_kernel<<<1024, 256>>>(p_msg, p_deg, n_net);
    scatter_kernel<<<cdiv(E1 * 32, 256), 256>>>(cell_h, e_c2n, e_c2n + E1,
                                                p_msg, p_deg, E1);
    mlp_mma_kernel<<<cdiv(n_net, BM), 256, SMEM_BYTES>>>(
        net_h, p_msg, p_deg, c2n_w1, c2n_b1, c2n_w2, c2n_b2,
        net_ln_g, net_ln_b, out_net, n_net, 1);

    // Stage 2: nets -> cells, cell_tmp = cell_h + MLP([cell_h, mean_msg])
    zero_kernel<<<1024, 256>>>(p_msg, p_deg, n_cell);
    scatter_kernel<<<cdiv(E2 * 32, 256), 256>>>(out_net, e_n2c, e_n2c + E2,
                                                p_msg, p_deg, E2);
    mlp_mma_kernel<<<cdiv(n_cell, BM), 256, SMEM_BYTES>>>(
        cell_h, p_msg, p_deg, n2c_w1, n2c_b1, n2c_w2, n2c_b2,
        (const float*)0, (const float*)0, p_tmp, n_cell, 0);

    // Stage 3: cells -> cells, cell_h' = LN(cell_tmp + MLP([cell_tmp, mean_msg]))
    zero_kernel<<<1024, 256>>>(p_msg, p_deg, n_cell);
    scatter_kernel<<<cdiv(E3 * 32, 256), 256>>>(p_tmp, e_c2c, e_c2c + E3,
                                                p_msg, p_deg, E3);
    mlp_mma_kernel<<<cdiv(n_cell, BM), 256, SMEM_BYTES>>>(
        p_tmp, p_msg, p_deg, c2c_w1, c2c_b1, c2c_w2, c2c_b2,
        cell_ln_g, cell_ln_b, out_cell, n_cell, 1);
}